// round 1
// baseline (speedup 1.0000x reference)
#include <cuda_runtime.h>
#include <math.h>

#define NV 4096
#define NG 2048
#define DD 64
#define KK 128
#define NBLK 4
#define EE 32768

// ---------------- scratch (device globals; no allocation allowed) ----------------
__device__ float g_rbf [NV * NG];       // [NV, NG]
__device__ float g_rbfT[NG * NV];       // [NG, NV]
__device__ float g_f   [NV * 192];      // [NV, 192] = [x | x_diff | gfeat]
__device__ float g_cat [NV * 128];      // [gX | gY]
__device__ float g_b2  [2 * NV * 64];   // [b_re ; b_im]
__device__ float g_h1  [NV * 64];
__device__ float g_h2  [NV * 64];
__device__ float g_xs  [KK * 64];       // x_spec
__device__ float g_cs  [KK * 64];       // coef * x_spec
__device__ float g_W   [2 * KK * 64];   // [Wre ; Wim]
__device__ float g_GE  [2 * NV * 128];  // [gradX@evecs ; gradY@evecs]
__device__ float g_gx  [NG * 64];
__device__ float g_hw  [NG * 64];
__device__ float g_agg [NG * 64];
__device__ float g_hg  [NG * 64];
__device__ float g_gx2 [NG * 64];
__device__ float g_deg [NG];
__device__ float g_dinv[NG];

// ---------------- generic N=64 GEMM: C[M,64] = A[M,KB] @ B[KB,64] ----------------
// blockIdx.z selects matrices: A = (z & zA) ? A1 : A0 ; B = (z & 1) ? B1 : B0 ;
// C += (z&1)*coff1 + (z>>1)*coff2.
// gridDim.y > 1 => split-K with atomicAdd (caller zero-inits C, no epilogue extras).
__global__ __launch_bounds__(128) void gemm64(
    const float* __restrict__ A0, const float* __restrict__ A1, int zA, int lda,
    const float* __restrict__ B0, const float* __restrict__ B1, int ldb,
    float* __restrict__ Cbase, int coff1, int coff2, int ldc,
    int KB, int kchunk,
    const float* __restrict__ bias,
    const float* __restrict__ resid, int ldr,
    int act)
{
    __shared__ float As[32][132];
    __shared__ float Bs[32][64];

    const int z = blockIdx.z;
    const float* A = (z & zA) ? A1 : A0;
    const float* B = (z & 1) ? B1 : B0;
    float* C = Cbase + (z & 1) * coff1 + (z >> 1) * coff2;

    const int tid  = threadIdx.x;
    const int tcol = tid & 7;
    const int trow = tid >> 3;
    const int m0   = blockIdx.x * 128;
    const int kbeg = blockIdx.y * kchunk;

    float acc[8][8];
#pragma unroll
    for (int i = 0; i < 8; i++)
#pragma unroll
        for (int j = 0; j < 8; j++) acc[i][j] = 0.0f;

    for (int kb = kbeg; kb < kbeg + kchunk; kb += 32) {
        // load A tile (128 rows x 32 k) transposed into smem
#pragma unroll
        for (int i = 0; i < 8; i++) {
            int q  = tid + i * 128;           // 0..1023 float4 ids
            int m  = q >> 3;
            int k4 = q & 7;
            float4 v = *(const float4*)(A + (size_t)(m0 + m) * lda + kb + k4 * 4);
            As[k4 * 4 + 0][m] = v.x;
            As[k4 * 4 + 1][m] = v.y;
            As[k4 * 4 + 2][m] = v.z;
            As[k4 * 4 + 3][m] = v.w;
        }
        // load B tile (32 x 64)
#pragma unroll
        for (int i = 0; i < 4; i++) {
            int q  = tid + i * 128;           // 0..511 float4 ids
            int k  = q >> 4;
            int n4 = q & 15;
            *(float4*)&Bs[k][n4 * 4] = *(const float4*)(B + (size_t)(kb + k) * ldb + n4 * 4);
        }
        __syncthreads();
#pragma unroll
        for (int k = 0; k < 32; k++) {
            float4 a0 = *(const float4*)&As[k][trow * 8];
            float4 a1 = *(const float4*)&As[k][trow * 8 + 4];
            float4 b0 = *(const float4*)&Bs[k][tcol * 8];
            float4 b1 = *(const float4*)&Bs[k][tcol * 8 + 4];
            float ar[8] = {a0.x, a0.y, a0.z, a0.w, a1.x, a1.y, a1.z, a1.w};
            float br[8] = {b0.x, b0.y, b0.z, b0.w, b1.x, b1.y, b1.z, b1.w};
#pragma unroll
            for (int i = 0; i < 8; i++)
#pragma unroll
                for (int j = 0; j < 8; j++)
                    acc[i][j] = fmaf(ar[i], br[j], acc[i][j]);
        }
        __syncthreads();
    }

    const bool split = (gridDim.y > 1);
#pragma unroll
    for (int i = 0; i < 8; i++) {
        int m  = m0 + trow * 8 + i;
        int n0 = tcol * 8;
        if (split) {
#pragma unroll
            for (int j = 0; j < 8; j++)
                atomicAdd(&C[(size_t)m * ldc + n0 + j], acc[i][j]);
        } else {
            float o[8];
#pragma unroll
            for (int j = 0; j < 8; j++) {
                float v = acc[i][j];
                if (bias)  v += bias[n0 + j];
                if (resid) v += resid[(size_t)m * ldr + n0 + j];
                if (act)   v = fmaxf(v, 0.0f);
                o[j] = v;
            }
            *(float4*)&C[(size_t)m * ldc + n0]     = make_float4(o[0], o[1], o[2], o[3]);
            *(float4*)&C[(size_t)m * ldc + n0 + 4] = make_float4(o[4], o[5], o[6], o[7]);
        }
    }
}

// ---------------- rbf coupling + transpose ----------------
__global__ void rbf_kernel(const float* __restrict__ vert, const float* __restrict__ gp,
                           float* __restrict__ rbf, float* __restrict__ rbfT)
{
    __shared__ float tile[32][33];
    int tx = threadIdx.x, ty = threadIdx.y;
    int g = blockIdx.x * 32 + tx;
    int v = blockIdx.y * 32 + ty;
    float vx = vert[v * 3], vy = vert[v * 3 + 1], vz = vert[v * 3 + 2];
    float gx = gp[g * 3],  gy = gp[g * 3 + 1],  gz = gp[g * 3 + 2];
    float dx = vx - gx, dy = vy - gy, dz = vz - gz;
    float dist = sqrtf(dx * dx + dy * dy + dz * dz);
    float r = expf(dist * (-1.0f / 2.5f));
    rbf[(size_t)v * NG + g] = r;
    tile[ty][tx] = r;
    __syncthreads();
    int g2 = blockIdx.x * 32 + ty;
    int v2 = blockIdx.y * 32 + tx;
    rbfT[(size_t)g2 * NV + v2] = tile[tx][ty];
}

// ---------------- spectral ops ----------------
__global__ void xspec_kernel(const float* __restrict__ f, const float* __restrict__ evecs,
                             const float* __restrict__ mass, float* __restrict__ xs)
{
    int k = blockIdx.x;        // 0..127
    int d = threadIdx.x;       // 0..63
    int v0 = blockIdx.y * (NV / 8);
    float acc = 0.0f;
#pragma unroll 4
    for (int v = v0; v < v0 + NV / 8; v++)
        acc += evecs[v * 128 + k] * mass[v] * f[v * 192 + d];
    atomicAdd(&xs[k * 64 + d], acc);
}

__global__ void cs_kernel(const float* __restrict__ xs, const float* __restrict__ evals,
                          const float* __restrict__ t, float* __restrict__ cs)
{
    int k = blockIdx.x, d = threadIdx.x;
    cs[k * 64 + d] = expf(-evals[k] * fmaxf(t[d], 1e-8f)) * xs[k * 64 + d];
}

__global__ void wcat_kernel(const float* __restrict__ are, const float* __restrict__ aim,
                            float* __restrict__ W /* [Wre ; Wim] */)
{
    int k = blockIdx.x, d = threadIdx.x;   // k 0..127, d 0..63
    float wre, wim;
    if (k < 64) { wre = are[k * 64 + d];        wim = aim[k * 64 + d]; }
    else        { wre = -aim[(k - 64) * 64 + d]; wim = are[(k - 64) * 64 + d]; }
    W[k * 64 + d]            = wre;
    W[KK * 64 + k * 64 + d]  = wim;
}

__global__ void gfeat_kernel(const float* __restrict__ cat, const float* __restrict__ b2,
                             float* __restrict__ f)
{
    int v = blockIdx.x, d = threadIdx.x;
    float gx = cat[v * 128 + d];
    float gy = cat[v * 128 + 64 + d];
    float bre = b2[v * 64 + d];
    float bim = b2[NV * 64 + v * 64 + d];
    f[v * 192 + 128 + d] = tanhf(gx * bre + gy * bim);
}

// ---------------- GCN helpers ----------------
__global__ void deg_kernel(const int* __restrict__ dst, float* __restrict__ deg)
{
    int e = blockIdx.x * 256 + threadIdx.x;
    atomicAdd(&deg[dst[e]], 1.0f);
}
__global__ void dinv_kernel(const float* __restrict__ deg, float* __restrict__ dinv)
{
    int i = blockIdx.x * 256 + threadIdx.x;
    dinv[i] = rsqrtf(deg[i] + 1.0f);   // +1 for self loop
}
__global__ void selfloop_kernel(const float* __restrict__ hw, const float* __restrict__ dinv,
                                float* __restrict__ agg)
{
    int i = blockIdx.x, d = threadIdx.x;
    float di = dinv[i];
    agg[i * 64 + d] = hw[i * 64 + d] * di * di;
}
__global__ void edge_kernel(const int* __restrict__ src, const int* __restrict__ dst,
                            const float* __restrict__ hw, const float* __restrict__ dinv,
                            float* __restrict__ agg)
{
    int e = blockIdx.x * 4 + (threadIdx.x >> 6);
    int d = threadIdx.x & 63;
    int s = src[e], t = dst[e];
    atomicAdd(&agg[t * 64 + d], hw[s * 64 + d] * dinv[s] * dinv[t]);
}
__global__ void finalize_kernel(const float* __restrict__ agg, const float* __restrict__ b,
                                float* __restrict__ out, int relu)
{
    int i = blockIdx.x, d = threadIdx.x;
    float v = agg[i * 64 + d] + b[d];
    out[i * 64 + d] = relu ? fmaxf(v, 0.0f) : v;
}

// ---------------- small dedicated kernels ----------------
__global__ void lin1_kernel(const float* __restrict__ sx, const float* __restrict__ w,
                            const float* __restrict__ b, float* __restrict__ f)
{
    int v = blockIdx.x, d = threadIdx.x;
    float acc = b[d];
#pragma unroll
    for (int j = 0; j < 5; j++) acc += sx[v * 5 + j] * w[j * 64 + d];
    f[v * 192 + d] = acc;
}

__global__ void zerocol_kernel(float* __restrict__ f)
{
    f[blockIdx.x * 192 + threadIdx.x] = 0.0f;
}

__global__ void out_kernel(const float* __restrict__ f, const float* __restrict__ w,
                           const float* __restrict__ b, float* __restrict__ out)
{
    int gid = blockIdx.x * 256 + threadIdx.x;   // 32768
    int v = gid >> 3, c = gid & 7;
    float acc = b[c];
#pragma unroll 8
    for (int d = 0; d < 64; d++) acc += f[v * 192 + d] * w[d * 8 + c];
    out[gid] = acc;
}

// ---------------- host ----------------
extern "C" void kernel_launch(void* const* d_in, const int* in_sizes, int n_in,
                              void* d_out, int out_size)
{
    static bool inited = false;
    static float *p_rbf, *p_rbfT, *p_f, *p_cat, *p_b2, *p_h1, *p_h2, *p_xs, *p_cs,
                 *p_W, *p_GE, *p_gx, *p_hw, *p_agg, *p_hg, *p_gx2, *p_deg, *p_dinv;
    if (!inited) {
        cudaGetSymbolAddress((void**)&p_rbf,  g_rbf);
        cudaGetSymbolAddress((void**)&p_rbfT, g_rbfT);
        cudaGetSymbolAddress((void**)&p_f,    g_f);
        cudaGetSymbolAddress((void**)&p_cat,  g_cat);
        cudaGetSymbolAddress((void**)&p_b2,   g_b2);
        cudaGetSymbolAddress((void**)&p_h1,   g_h1);
        cudaGetSymbolAddress((void**)&p_h2,   g_h2);
        cudaGetSymbolAddress((void**)&p_xs,   g_xs);
        cudaGetSymbolAddress((void**)&p_cs,   g_cs);
        cudaGetSymbolAddress((void**)&p_W,    g_W);
        cudaGetSymbolAddress((void**)&p_GE,   g_GE);
        cudaGetSymbolAddress((void**)&p_gx,   g_gx);
        cudaGetSymbolAddress((void**)&p_hw,   g_hw);
        cudaGetSymbolAddress((void**)&p_agg,  g_agg);
        cudaGetSymbolAddress((void**)&p_hg,   g_hg);
        cudaGetSymbolAddress((void**)&p_gx2,  g_gx2);
        cudaGetSymbolAddress((void**)&p_deg,  g_deg);
        cudaGetSymbolAddress((void**)&p_dinv, g_dinv);
        inited = true;
    }

    const float* surf_x    = (const float*)d_in[0];
    const float* mass      = (const float*)d_in[1];
    const float* evals     = (const float*)d_in[2];
    const float* evecs     = (const float*)d_in[3];
    const float* gradX     = (const float*)d_in[4];
    const float* gradY     = (const float*)d_in[5];
    const float* vertices  = (const float*)d_in[6];
    const float* graph_pos = (const float*)d_in[8];
    const float* lin1_w    = (const float*)d_in[9];
    const float* lin1_b    = (const float*)d_in[10];
    const float* last_w    = (const float*)d_in[13];
    const float* last_b    = (const float*)d_in[14];
    const float* diff_time = (const float*)d_in[15];
    const float* A_re      = (const float*)d_in[16];
    const float* A_im      = (const float*)d_in[17];
    const float* mlp_w0    = (const float*)d_in[18];
    const float* mlp_b0    = (const float*)d_in[19];
    const float* mlp_w1    = (const float*)d_in[20];
    const float* mlp_b1    = (const float*)d_in[21];
    const float* mlp_w2    = (const float*)d_in[22];
    const float* mlp_b2    = (const float*)d_in[23];
    const float* gcn_w1    = (const float*)d_in[24];
    const float* gcn_b1    = (const float*)d_in[25];
    const float* gcn_w2    = (const float*)d_in[26];
    const float* gcn_b2    = (const float*)d_in[27];
    const int*   eidx      = (const int*)d_in[28];
    const int*   e_src     = eidx;
    const int*   e_dst     = eidx + EE;
    float* out = (float*)d_out;

    // ---- one-time per call: rbf, degrees, lin1 init, GXE/GYE precompute ----
    rbf_kernel<<<dim3(NG / 32, NV / 32), dim3(32, 32)>>>(vertices, graph_pos, p_rbf, p_rbfT);

    cudaMemsetAsync(p_deg, 0, NG * sizeof(float));
    deg_kernel<<<EE / 256, 256>>>(e_dst, p_deg);
    dinv_kernel<<<NG / 256, 256>>>(p_deg, p_dinv);

    lin1_kernel<<<NV, 64>>>(surf_x, lin1_w, lin1_b, p_f);

    // GE = [gradX@evecs ; gradY@evecs]  (z: bit1 -> gradY, bit0 -> evec col half)
    gemm64<<<dim3(NV / 128, 1, 4), 128>>>(
        gradX, gradY, /*zA=*/2, NV,
        evecs, evecs + 64, 128,
        p_GE, /*coff1=*/64, /*coff2=*/NV * 128, /*ldc=*/128,
        NV, NV, nullptr, nullptr, 0, 0);

    for (int blk = 0; blk < NBLK; blk++) {
        const float* t   = diff_time + blk * 64;
        const float* are = A_re + blk * 64 * 64;
        const float* aim = A_im + blk * 64 * 64;
        const float* w0  = mlp_w0 + blk * 192 * 64;
        const float* b0  = mlp_b0 + blk * 64;
        const float* w1  = mlp_w1 + blk * 64 * 64;
        const float* b1  = mlp_b1 + blk * 64;
        const float* w2  = mlp_w2 + blk * 64 * 64;
        const float* b2  = mlp_b2 + blk * 64;
        const float* gw1 = gcn_w1 + blk * 64 * 64;
        const float* gb1 = gcn_b1 + blk * 64;
        const float* gw2 = gcn_w2 + blk * 64 * 64;
        const float* gb2 = gcn_b2 + blk * 64;

        // x_spec = evecs^T @ (x * mass)
        cudaMemsetAsync(p_xs, 0, KK * 64 * sizeof(float));
        xspec_kernel<<<dim3(KK, 8), 64>>>(p_f, evecs, mass, p_xs);
        cs_kernel<<<KK, 64>>>(p_xs, evals, t, p_cs);

        // x_diff = evecs @ cs -> f[:,64:128]
        gemm64<<<dim3(NV / 128, 1, 1), 128>>>(
            evecs, evecs, 0, 128, p_cs, p_cs, 64,
            p_f + 64, 0, 0, 192, KK, KK, nullptr, nullptr, 0, 0);

        // gX|gY = GE @ cs -> g_cat
        gemm64<<<dim3(NV / 128, 1, 2), 128>>>(
            p_GE, p_GE + NV * 128, /*zA=*/1, 128, p_cs, p_cs, 64,
            p_cat, 64, 0, 128, KK, KK, nullptr, nullptr, 0, 0);

        // b_re|b_im = g_cat @ [Wre|Wim]
        wcat_kernel<<<KK, 64>>>(are, aim, p_W);
        gemm64<<<dim3(NV / 128, 1, 2), 128>>>(
            p_cat, p_cat, 0, 128, p_W, p_W + KK * 64, 64,
            p_b2, NV * 64, 0, 64, KK, KK, nullptr, nullptr, 0, 0);

        gfeat_kernel<<<NV, 64>>>(p_cat, p_b2, p_f);

        // MLP: h1 = relu(f@w0+b0); h2 = relu(h1@w1+b1); x' = h2@w2+b2 + x
        gemm64<<<dim3(NV / 128, 1, 1), 128>>>(
            p_f, p_f, 0, 192, w0, w0, 64, p_h1, 0, 0, 64, 192, 192, b0, nullptr, 0, 1);
        gemm64<<<dim3(NV / 128, 1, 1), 128>>>(
            p_h1, p_h1, 0, 64, w1, w1, 64, p_h2, 0, 0, 64, 64, 64, b1, nullptr, 0, 1);
        gemm64<<<dim3(NV / 128, 1, 1), 128>>>(
            p_h2, p_h2, 0, 64, w2, w2, 64, p_f, 0, 0, 192, 64, 64, b2, p_f, 192, 0);

        // gx = rbf^T @ diff_x (split-K 8)
        cudaMemsetAsync(p_gx, 0, NG * 64 * sizeof(float));
        gemm64<<<dim3(NG / 128, 8, 1), 128>>>(
            p_rbfT, p_rbfT, 0, NV, p_f, p_f, 192,
            p_gx, 0, 0, 64, NV, NV / 8, nullptr, nullptr, 0, 0);

        // GCN layer 1 (relu)
        gemm64<<<dim3(NG / 128, 1, 1), 128>>>(
            p_gx, p_gx, 0, 64, gw1, gw1, 64, p_hw, 0, 0, 64, 64, 64, nullptr, nullptr, 0, 0);
        selfloop_kernel<<<NG, 64>>>(p_hw, p_dinv, p_agg);
        edge_kernel<<<EE / 4, 256>>>(e_src, e_dst, p_hw, p_dinv, p_agg);
        finalize_kernel<<<NG, 64>>>(p_agg, gb1, p_hg, 1);

        // GCN layer 2 (no relu)
        gemm64<<<dim3(NG / 128, 1, 1), 128>>>(
            p_hg, p_hg, 0, 64, gw2, gw2, 64, p_hw, 0, 0, 64, 64, 64, nullptr, nullptr, 0, 0);
        selfloop_kernel<<<NG, 64>>>(p_hw, p_dinv, p_agg);
        edge_kernel<<<EE / 4, 256>>>(e_src, e_dst, p_hw, p_dinv, p_agg);
        finalize_kernel<<<NG, 64>>>(p_agg, gb2, p_gx2, 0);

        // diff_x = rbf @ gx2 -> f[:,0:64]  (split-K 4)
        zerocol_kernel<<<NV, 64>>>(p_f);
        gemm64<<<dim3(NV / 128, 4, 1), 128>>>(
            p_rbf, p_rbf, 0, NG, p_gx2, p_gx2, 64,
            p_f, 0, 0, 192, NG, NG / 4, nullptr, nullptr, 0, 0);
    }

    out_kernel<<<(NV * 8) / 256, 256>>>(p_f, last_w, last_b, out);
}

// round 2
// speedup vs baseline: 1.7121x; 1.7121x over previous
#include <cuda_runtime.h>
#include <math.h>
#include <stdint.h>

#define NV 4096
#define NG 2048
#define DD 64
#define KK 128
#define NBLK 4
#define EE 32768

// ---------------- scratch (device globals; no allocation allowed) ----------------
__device__ float g_rbf [NV * NG];       // [NV, NG]
__device__ float g_rbfT[NG * NV];       // [NG, NV]
__device__ float g_f   [NV * 192];      // [NV, 192] = [x | x_diff | gfeat]
__device__ float g_cat [NV * 128];      // [gX | gY]
__device__ float g_b2  [2 * NV * 64];   // [b_re ; b_im]
__device__ float g_h1  [NV * 64];
__device__ float g_h2  [NV * 64];
__device__ float g_xs  [KK * 64];       // x_spec
__device__ float g_cs  [KK * 64];       // coef * x_spec
__device__ float g_W   [2 * KK * 64];   // [Wre ; Wim]
__device__ float g_GE  [2 * NV * 128];  // [gradX@evecs ; gradY@evecs]
__device__ float g_gx  [NG * 64];
__device__ float g_hw  [NG * 64];
__device__ float g_agg [NG * 64];
__device__ float g_hg  [NG * 64];
__device__ float g_gx2 [NG * 64];
__device__ float g_deg [NG];
__device__ float g_dinv[NG];

// ---------------- tf32 tensor-core helpers ----------------
__device__ __forceinline__ uint32_t cvt_tf32(float x) {
    uint32_t r;
    asm("cvt.rna.tf32.f32 %0, %1;" : "=r"(r) : "f"(x));
    return r;
}

__device__ __forceinline__ void mma_tf32(float* c, const uint32_t* a, const uint32_t* b) {
    asm volatile(
        "mma.sync.aligned.m16n8k8.row.col.f32.tf32.tf32.f32 "
        "{%0,%1,%2,%3}, {%4,%5,%6,%7}, {%8,%9}, {%0,%1,%2,%3};"
        : "+f"(c[0]), "+f"(c[1]), "+f"(c[2]), "+f"(c[3])
        : "r"(a[0]), "r"(a[1]), "r"(a[2]), "r"(a[3]), "r"(b[0]), "r"(b[1]));
}

// ---------------- generic N=64 GEMM (tensor-core tf32) ----------------
// C[M,64] = A[M,KB] @ B[KB,64]
// blockIdx.z selects matrices: A = (z & zA) ? A1 : A0 ; B = (z & 1) ? B1 : B0 ;
// C += (z&1)*coff1 + (z>>1)*coff2.
// gridDim.y > 1 => split-K with atomicAdd (caller zero-inits C, no epilogue extras).
__global__ __launch_bounds__(128) void gemm64(
    const float* __restrict__ A0, const float* __restrict__ A1, int zA, int lda,
    const float* __restrict__ B0, const float* __restrict__ B1, int ldb,
    float* __restrict__ Cbase, int coff1, int coff2, int ldc,
    int KB, int kchunk,
    const float* __restrict__ bias,
    const float* __restrict__ resid, int ldr,
    int act)
{
    __shared__ float As[128][36];   // stride 36: bank = (4*row + col) % 32 -> conflict-free frags
    __shared__ float Bs[32][72];    // stride 72: bank = (8*k + n) % 32     -> conflict-free frags

    const int z = blockIdx.z;
    const float* A = (z & zA) ? A1 : A0;
    const float* B = (z & 1) ? B1 : B0;
    float* C = Cbase + (z & 1) * coff1 + (z >> 1) * coff2;

    const int tid    = threadIdx.x;
    const int warp   = tid >> 5;
    const int lane   = tid & 31;
    const int g      = lane >> 2;   // group (row within 8)
    const int tg     = lane & 3;    // thread-in-group
    const int m0     = blockIdx.x * 128;
    const int warp_m = warp * 32;
    const int kbeg   = blockIdx.y * kchunk;

    float c[2][8][4];
#pragma unroll
    for (int mi = 0; mi < 2; mi++)
#pragma unroll
        for (int ni = 0; ni < 8; ni++)
#pragma unroll
            for (int r = 0; r < 4; r++) c[mi][ni][r] = 0.0f;

    for (int kb = kbeg; kb < kbeg + kchunk; kb += 32) {
        // A tile: 128 rows x 32 cols, row-major in smem
#pragma unroll
        for (int i = 0; i < 8; i++) {
            int q  = tid + i * 128;           // 0..1023 float4 ids
            int m  = q >> 3;
            int k4 = q & 7;
            float4 v = *(const float4*)(A + (size_t)(m0 + m) * lda + kb + k4 * 4);
            *(float4*)&As[m][k4 * 4] = v;
        }
        // B tile: 32 x 64
#pragma unroll
        for (int i = 0; i < 4; i++) {
            int q  = tid + i * 128;           // 0..511 float4 ids
            int k  = q >> 4;
            int n4 = q & 15;
            *(float4*)&Bs[k][n4 * 4] = *(const float4*)(B + (size_t)(kb + k) * ldb + n4 * 4);
        }
        __syncthreads();

#pragma unroll
        for (int k8 = 0; k8 < 32; k8 += 8) {
            uint32_t a[2][4];
#pragma unroll
            for (int mi = 0; mi < 2; mi++) {
                int r0 = warp_m + mi * 16 + g;
                a[mi][0] = cvt_tf32(As[r0][k8 + tg]);
                a[mi][1] = cvt_tf32(As[r0 + 8][k8 + tg]);
                a[mi][2] = cvt_tf32(As[r0][k8 + tg + 4]);
                a[mi][3] = cvt_tf32(As[r0 + 8][k8 + tg + 4]);
            }
            uint32_t b[8][2];
#pragma unroll
            for (int ni = 0; ni < 8; ni++) {
                b[ni][0] = cvt_tf32(Bs[k8 + tg][ni * 8 + g]);
                b[ni][1] = cvt_tf32(Bs[k8 + tg + 4][ni * 8 + g]);
            }
#pragma unroll
            for (int mi = 0; mi < 2; mi++)
#pragma unroll
                for (int ni = 0; ni < 8; ni++)
                    mma_tf32(c[mi][ni], a[mi], b[ni]);
        }
        __syncthreads();
    }

    const bool split = (gridDim.y > 1);
#pragma unroll
    for (int mi = 0; mi < 2; mi++) {
#pragma unroll
        for (int rr = 0; rr < 2; rr++) {
            int m = m0 + warp_m + mi * 16 + g + rr * 8;
#pragma unroll
            for (int ni = 0; ni < 8; ni++) {
                int n = ni * 8 + tg * 2;
                float v0 = c[mi][ni][rr * 2 + 0];
                float v1 = c[mi][ni][rr * 2 + 1];
                if (split) {
                    atomicAdd(&C[(size_t)m * ldc + n],     v0);
                    atomicAdd(&C[(size_t)m * ldc + n + 1], v1);
                } else {
                    if (bias)  { v0 += bias[n]; v1 += bias[n + 1]; }
                    if (resid) { v0 += resid[(size_t)m * ldr + n];
                                 v1 += resid[(size_t)m * ldr + n + 1]; }
                    if (act)   { v0 = fmaxf(v0, 0.0f); v1 = fmaxf(v1, 0.0f); }
                    *(float2*)&C[(size_t)m * ldc + n] = make_float2(v0, v1);
                }
            }
        }
    }
}

// ---------------- rbf coupling + transpose ----------------
__global__ void rbf_kernel(const float* __restrict__ vert, const float* __restrict__ gp,
                           float* __restrict__ rbf, float* __restrict__ rbfT)
{
    __shared__ float tile[32][33];
    int tx = threadIdx.x, ty = threadIdx.y;
    int g = blockIdx.x * 32 + tx;
    int v = blockIdx.y * 32 + ty;
    float vx = vert[v * 3], vy = vert[v * 3 + 1], vz = vert[v * 3 + 2];
    float gx = gp[g * 3],  gy = gp[g * 3 + 1],  gz = gp[g * 3 + 2];
    float dx = vx - gx, dy = vy - gy, dz = vz - gz;
    float dist = sqrtf(dx * dx + dy * dy + dz * dz);
    float r = expf(dist * (-1.0f / 2.5f));
    rbf[(size_t)v * NG + g] = r;
    tile[ty][tx] = r;
    __syncthreads();
    int g2 = blockIdx.x * 32 + ty;
    int v2 = blockIdx.y * 32 + tx;
    rbfT[(size_t)g2 * NV + v2] = tile[tx][ty];
}

// ---------------- spectral ops ----------------
__global__ void xspec_kernel(const float* __restrict__ f, const float* __restrict__ evecs,
                             const float* __restrict__ mass, float* __restrict__ xs)
{
    int k = blockIdx.x;        // 0..127
    int d = threadIdx.x;       // 0..63
    int v0 = blockIdx.y * (NV / 8);
    float acc = 0.0f;
#pragma unroll 4
    for (int v = v0; v < v0 + NV / 8; v++)
        acc += evecs[v * 128 + k] * mass[v] * f[v * 192 + d];
    atomicAdd(&xs[k * 64 + d], acc);
}

__global__ void cs_kernel(const float* __restrict__ xs, const float* __restrict__ evals,
                          const float* __restrict__ t, float* __restrict__ cs)
{
    int k = blockIdx.x, d = threadIdx.x;
    cs[k * 64 + d] = expf(-evals[k] * fmaxf(t[d], 1e-8f)) * xs[k * 64 + d];
}

__global__ void wcat_kernel(const float* __restrict__ are, const float* __restrict__ aim,
                            float* __restrict__ W /* [Wre ; Wim] */)
{
    int k = blockIdx.x, d = threadIdx.x;   // k 0..127, d 0..63
    float wre, wim;
    if (k < 64) { wre = are[k * 64 + d];         wim = aim[k * 64 + d]; }
    else        { wre = -aim[(k - 64) * 64 + d]; wim = are[(k - 64) * 64 + d]; }
    W[k * 64 + d]           = wre;
    W[KK * 64 + k * 64 + d] = wim;
}

__global__ void gfeat_kernel(const float* __restrict__ cat, const float* __restrict__ b2,
                             float* __restrict__ f)
{
    int v = blockIdx.x, d = threadIdx.x;
    float gx = cat[v * 128 + d];
    float gy = cat[v * 128 + 64 + d];
    float bre = b2[v * 64 + d];
    float bim = b2[NV * 64 + v * 64 + d];
    f[v * 192 + 128 + d] = tanhf(gx * bre + gy * bim);
}

// ---------------- GCN helpers ----------------
__global__ void deg_kernel(const int* __restrict__ dst, float* __restrict__ deg)
{
    int e = blockIdx.x * 256 + threadIdx.x;
    atomicAdd(&deg[dst[e]], 1.0f);
}
__global__ void dinv_kernel(const float* __restrict__ deg, float* __restrict__ dinv)
{
    int i = blockIdx.x * 256 + threadIdx.x;
    dinv[i] = rsqrtf(deg[i] + 1.0f);   // +1 for self loop
}
__global__ void selfloop_kernel(const float* __restrict__ hw, const float* __restrict__ dinv,
                                float* __restrict__ agg)
{
    int i = blockIdx.x, d = threadIdx.x;
    float di = dinv[i];
    agg[i * 64 + d] = hw[i * 64 + d] * di * di;
}
__global__ void edge_kernel(const int* __restrict__ src, const int* __restrict__ dst,
                            const float* __restrict__ hw, const float* __restrict__ dinv,
                            float* __restrict__ agg)
{
    int e = blockIdx.x * 4 + (threadIdx.x >> 6);
    int d = threadIdx.x & 63;
    int s = src[e], t = dst[e];
    atomicAdd(&agg[t * 64 + d], hw[s * 64 + d] * dinv[s] * dinv[t]);
}
__global__ void finalize_kernel(const float* __restrict__ agg, const float* __restrict__ b,
                                float* __restrict__ out, int relu)
{
    int i = blockIdx.x, d = threadIdx.x;
    float v = agg[i * 64 + d] + b[d];
    out[i * 64 + d] = relu ? fmaxf(v, 0.0f) : v;
}

// ---------------- small dedicated kernels ----------------
__global__ void lin1_kernel(const float* __restrict__ sx, const float* __restrict__ w,
                            const float* __restrict__ b, float* __restrict__ f)
{
    int v = blockIdx.x, d = threadIdx.x;
    float acc = b[d];
#pragma unroll
    for (int j = 0; j < 5; j++) acc += sx[v * 5 + j] * w[j * 64 + d];
    f[v * 192 + d] = acc;
}

__global__ void zerocol_kernel(float* __restrict__ f)
{
    f[blockIdx.x * 192 + threadIdx.x] = 0.0f;
}

__global__ void out_kernel(const float* __restrict__ f, const float* __restrict__ w,
                           const float* __restrict__ b, float* __restrict__ out)
{
    int gid = blockIdx.x * 256 + threadIdx.x;   // 32768
    int v = gid >> 3, c = gid & 7;
    float acc = b[c];
#pragma unroll 8
    for (int d = 0; d < 64; d++) acc += f[v * 192 + d] * w[d * 8 + c];
    out[gid] = acc;
}

// ---------------- host ----------------
extern "C" void kernel_launch(void* const* d_in, const int* in_sizes, int n_in,
                              void* d_out, int out_size)
{
    static bool inited = false;
    static float *p_rbf, *p_rbfT, *p_f, *p_cat, *p_b2, *p_h1, *p_h2, *p_xs, *p_cs,
                 *p_W, *p_GE, *p_gx, *p_hw, *p_agg, *p_hg, *p_gx2, *p_deg, *p_dinv;
    if (!inited) {
        cudaGetSymbolAddress((void**)&p_rbf,  g_rbf);
        cudaGetSymbolAddress((void**)&p_rbfT, g_rbfT);
        cudaGetSymbolAddress((void**)&p_f,    g_f);
        cudaGetSymbolAddress((void**)&p_cat,  g_cat);
        cudaGetSymbolAddress((void**)&p_b2,   g_b2);
        cudaGetSymbolAddress((void**)&p_h1,   g_h1);
        cudaGetSymbolAddress((void**)&p_h2,   g_h2);
        cudaGetSymbolAddress((void**)&p_xs,   g_xs);
        cudaGetSymbolAddress((void**)&p_cs,   g_cs);
        cudaGetSymbolAddress((void**)&p_W,    g_W);
        cudaGetSymbolAddress((void**)&p_GE,   g_GE);
        cudaGetSymbolAddress((void**)&p_gx,   g_gx);
        cudaGetSymbolAddress((void**)&p_hw,   g_hw);
        cudaGetSymbolAddress((void**)&p_agg,  g_agg);
        cudaGetSymbolAddress((void**)&p_hg,   g_hg);
        cudaGetSymbolAddress((void**)&p_gx2,  g_gx2);
        cudaGetSymbolAddress((void**)&p_deg,  g_deg);
        cudaGetSymbolAddress((void**)&p_dinv, g_dinv);
        inited = true;
    }

    const float* surf_x    = (const float*)d_in[0];
    const float* mass      = (const float*)d_in[1];
    const float* evals     = (const float*)d_in[2];
    const float* evecs     = (const float*)d_in[3];
    const float* gradX     = (const float*)d_in[4];
    const float* gradY     = (const float*)d_in[5];
    const float* vertices  = (const float*)d_in[6];
    const float* graph_pos = (const float*)d_in[8];
    const float* lin1_w    = (const float*)d_in[9];
    const float* lin1_b    = (const float*)d_in[10];
    const float* last_w    = (const float*)d_in[13];
    const float* last_b    = (const float*)d_in[14];
    const float* diff_time = (const float*)d_in[15];
    const float* A_re      = (const float*)d_in[16];
    const float* A_im      = (const float*)d_in[17];
    const float* mlp_w0    = (const float*)d_in[18];
    const float* mlp_b0    = (const float*)d_in[19];
    const float* mlp_w1    = (const float*)d_in[20];
    const float* mlp_b1    = (const float*)d_in[21];
    const float* mlp_w2    = (const float*)d_in[22];
    const float* mlp_b2    = (const float*)d_in[23];
    const float* gcn_w1    = (const float*)d_in[24];
    const float* gcn_b1    = (const float*)d_in[25];
    const float* gcn_w2    = (const float*)d_in[26];
    const float* gcn_b2    = (const float*)d_in[27];
    const int*   eidx      = (const int*)d_in[28];
    const int*   e_src     = eidx;
    const int*   e_dst     = eidx + EE;
    float* out = (float*)d_out;

    // ---- one-time per call: rbf, degrees, lin1 init, GXE/GYE precompute ----
    rbf_kernel<<<dim3(NG / 32, NV / 32), dim3(32, 32)>>>(vertices, graph_pos, p_rbf, p_rbfT);

    cudaMemsetAsync(p_deg, 0, NG * sizeof(float));
    deg_kernel<<<EE / 256, 256>>>(e_dst, p_deg);
    dinv_kernel<<<NG / 256, 256>>>(p_deg, p_dinv);

    lin1_kernel<<<NV, 64>>>(surf_x, lin1_w, lin1_b, p_f);

    // GE = [gradX@evecs ; gradY@evecs]  (z: bit1 -> gradY, bit0 -> evec col half)
    gemm64<<<dim3(NV / 128, 1, 4), 128>>>(
        gradX, gradY, /*zA=*/2, NV,
        evecs, evecs + 64, 128,
        p_GE, /*coff1=*/64, /*coff2=*/NV * 128, /*ldc=*/128,
        NV, NV, nullptr, nullptr, 0, 0);

    for (int blk = 0; blk < NBLK; blk++) {
        const float* t   = diff_time + blk * 64;
        const float* are = A_re + blk * 64 * 64;
        const float* aim = A_im + blk * 64 * 64;
        const float* w0  = mlp_w0 + blk * 192 * 64;
        const float* b0  = mlp_b0 + blk * 64;
        const float* w1  = mlp_w1 + blk * 64 * 64;
        const float* b1  = mlp_b1 + blk * 64;
        const float* w2  = mlp_w2 + blk * 64 * 64;
        const float* b2  = mlp_b2 + blk * 64;
        const float* gw1 = gcn_w1 + blk * 64 * 64;
        const float* gb1 = gcn_b1 + blk * 64;
        const float* gw2 = gcn_w2 + blk * 64 * 64;
        const float* gb2 = gcn_b2 + blk * 64;

        // x_spec = evecs^T @ (x * mass)
        cudaMemsetAsync(p_xs, 0, KK * 64 * sizeof(float));
        xspec_kernel<<<dim3(KK, 8), 64>>>(p_f, evecs, mass, p_xs);
        cs_kernel<<<KK, 64>>>(p_xs, evals, t, p_cs);

        // x_diff = evecs @ cs -> f[:,64:128]
        gemm64<<<dim3(NV / 128, 1, 1), 128>>>(
            evecs, evecs, 0, 128, p_cs, p_cs, 64,
            p_f + 64, 0, 0, 192, KK, KK, nullptr, nullptr, 0, 0);

        // gX|gY = GE @ cs -> g_cat
        gemm64<<<dim3(NV / 128, 1, 2), 128>>>(
            p_GE, p_GE + NV * 128, /*zA=*/1, 128, p_cs, p_cs, 64,
            p_cat, 64, 0, 128, KK, KK, nullptr, nullptr, 0, 0);

        // b_re|b_im = g_cat @ [Wre|Wim]
        wcat_kernel<<<KK, 64>>>(are, aim, p_W);
        gemm64<<<dim3(NV / 128, 1, 2), 128>>>(
            p_cat, p_cat, 0, 128, p_W, p_W + KK * 64, 64,
            p_b2, NV * 64, 0, 64, KK, KK, nullptr, nullptr, 0, 0);

        gfeat_kernel<<<NV, 64>>>(p_cat, p_b2, p_f);

        // MLP: h1 = relu(f@w0+b0); h2 = relu(h1@w1+b1); x' = h2@w2+b2 + x
        gemm64<<<dim3(NV / 128, 1, 1), 128>>>(
            p_f, p_f, 0, 192, w0, w0, 64, p_h1, 0, 0, 64, 192, 192, b0, nullptr, 0, 1);
        gemm64<<<dim3(NV / 128, 1, 1), 128>>>(
            p_h1, p_h1, 0, 64, w1, w1, 64, p_h2, 0, 0, 64, 64, 64, b1, nullptr, 0, 1);
        gemm64<<<dim3(NV / 128, 1, 1), 128>>>(
            p_h2, p_h2, 0, 64, w2, w2, 64, p_f, 0, 0, 192, 64, 64, b2, p_f, 192, 0);

        // gx = rbf^T @ diff_x (split-K 8)
        cudaMemsetAsync(p_gx, 0, NG * 64 * sizeof(float));
        gemm64<<<dim3(NG / 128, 8, 1), 128>>>(
            p_rbfT, p_rbfT, 0, NV, p_f, p_f, 192,
            p_gx, 0, 0, 64, NV, NV / 8, nullptr, nullptr, 0, 0);

        // GCN layer 1 (relu)
        gemm64<<<dim3(NG / 128, 1, 1), 128>>>(
            p_gx, p_gx, 0, 64, gw1, gw1, 64, p_hw, 0, 0, 64, 64, 64, nullptr, nullptr, 0, 0);
        selfloop_kernel<<<NG, 64>>>(p_hw, p_dinv, p_agg);
        edge_kernel<<<EE / 4, 256>>>(e_src, e_dst, p_hw, p_dinv, p_agg);
        finalize_kernel<<<NG, 64>>>(p_agg, gb1, p_hg, 1);

        // GCN layer 2 (no relu)
        gemm64<<<dim3(NG / 128, 1, 1), 128>>>(
            p_hg, p_hg, 0, 64, gw2, gw2, 64, p_hw, 0, 0, 64, 64, 64, nullptr, nullptr, 0, 0);
        selfloop_kernel<<<NG, 64>>>(p_hw, p_dinv, p_agg);
        edge_kernel<<<EE / 4, 256>>>(e_src, e_dst, p_hw, p_dinv, p_agg);
        finalize_kernel<<<NG, 64>>>(p_agg, gb2, p_gx2, 0);

        // diff_x = rbf @ gx2 -> f[:,0:64]  (split-K 4)
        zerocol_kernel<<<NV, 64>>>(p_f);
        gemm64<<<dim3(NV / 128, 4, 1), 128>>>(
            p_rbf, p_rbf, 0, NG, p_gx2, p_gx2, 64,
            p_f, 0, 0, 192, NG, NG / 4, nullptr, nullptr, 0, 0);
    }

    out_kernel<<<(NV * 8) / 256, 256>>>(p_f, last_w, last_b, out);
}